// round 13
// baseline (speedup 1.0000x reference)
#include <cuda_runtime.h>
#include <math.h>

#define DH 64
#define DC 3

typedef unsigned long long ull;

// Lane-interleaved generators: float4 index ((gen*2+rr)*16+q)*32 + l holds
// S_gen[row = l+32*rr][cols 4q..4q+3], S = 0.5*(L - L^T).  3*2*16*32 float4s.
__device__ float4 g_skew_il[DC * 2 * 16 * 32];
// Lane-interleaved P_sp: float4 index (rr*16+q)*32 + l.
__device__ float4 g_psp_il[2 * 16 * 32];
// Gram matrix of generators: [S0.S0, S0.S1, S0.S2, S1.S1, S1.S2, S2.S2]
__device__ float g_gram[6];
// P == identity flag
__device__ int g_pident;
// Chebyshev coefficient table: 64 rho-quanta (rho_q = 0.5*(qi), qi=1..64),
// 48 floats each: coef[k] = (k==0?1:2)*J_k(rho_q)/norm, zero beyond kmax.
__device__ float g_ctab[64 * 48];

__global__ void build_il_kernel(const float* __restrict__ L,
                                const float* __restrict__ P) {
    int idx = blockIdx.x * blockDim.x + threadIdx.x;
    if (idx < DC * 2 * 16 * 32) {
        int l   = idx & 31;
        int q   = (idx >> 5) & 15;
        int rr  = (idx >> 9) & 1;
        int g   = idx >> 10;
        int row = l + 32 * rr;
        float4 v;
        const float* Lg = L + g * DH * DH;
        int c0 = 4 * q;
        v.x = 0.5f * (Lg[row * DH + c0 + 0] - Lg[(c0 + 0) * DH + row]);
        v.y = 0.5f * (Lg[row * DH + c0 + 1] - Lg[(c0 + 1) * DH + row]);
        v.z = 0.5f * (Lg[row * DH + c0 + 2] - Lg[(c0 + 2) * DH + row]);
        v.w = 0.5f * (Lg[row * DH + c0 + 3] - Lg[(c0 + 3) * DH + row]);
        g_skew_il[idx] = v;
    }
    int pidx = idx - DC * 2 * 16 * 32;
    if (pidx >= 0 && pidx < 2 * 16 * 32) {
        int l   = pidx & 31;
        int q   = (pidx >> 5) & 15;
        int rr  = (pidx >> 9) & 1;
        int row = l + 32 * rr;
        const float4* pr = reinterpret_cast<const float4*>(P + row * DH);
        g_psp_il[pidx] = pr[q];
    }
}

// Gram matrix + P-identity check (single block).
__global__ void gram_kernel(const float* __restrict__ P) {
    __shared__ float red[8][6];
    __shared__ int nid[8];
    int t = threadIdx.x;   // 256 threads
    float g[6] = {0.f, 0.f, 0.f, 0.f, 0.f, 0.f};
    int notid = 0;
    for (int j = t; j < 1024; j += 256) {
        float4 a = g_skew_il[j];
        float4 b = g_skew_il[1024 + j];
        float4 c = g_skew_il[2048 + j];
        g[0] += a.x*a.x + a.y*a.y + a.z*a.z + a.w*a.w;
        g[1] += a.x*b.x + a.y*b.y + a.z*b.z + a.w*b.w;
        g[2] += a.x*c.x + a.y*c.y + a.z*c.z + a.w*c.w;
        g[3] += b.x*b.x + b.y*b.y + b.z*b.z + b.w*b.w;
        g[4] += b.x*c.x + b.y*c.y + b.z*c.z + b.w*c.w;
        g[5] += c.x*c.x + c.y*c.y + c.z*c.z + c.w*c.w;
    }
    for (int j = t; j < DH * DH; j += 256) {
        float expd = ((j >> 6) == (j & 63)) ? 1.0f : 0.0f;
        if (P[j] != expd) notid = 1;
    }
    #pragma unroll
    for (int off = 16; off >= 1; off >>= 1) {
        #pragma unroll
        for (int i = 0; i < 6; i++)
            g[i] += __shfl_xor_sync(0xffffffffu, g[i], off);
        notid |= __shfl_xor_sync(0xffffffffu, notid, off);
    }
    if ((t & 31) == 0) {
        #pragma unroll
        for (int i = 0; i < 6; i++) red[t >> 5][i] = g[i];
        nid[t >> 5] = notid;
    }
    __syncthreads();
    if (t < 6) {
        float s = 0.f;
        #pragma unroll
        for (int w = 0; w < 8; w++) s += red[w][t];
        g_gram[t] = s;
    }
    if (t == 32) {
        int n = 0;
        #pragma unroll
        for (int w = 0; w < 8; w++) n |= nid[w];
        g_pident = !n;
    }
}

// Coefficient table: thread t handles qi = t+1, rho_q = 0.5*(t+1).
__global__ void coef_kernel() {
    int t = blockIdx.x * blockDim.x + threadIdx.x;
    if (t >= 64) return;
    float rho = 0.5f * (float)(t + 1);
    int kmax = (t + 2) / 2 + 8;            // ceil(rho)+8 = ceil((t+1)/2)+8
    if (kmax > 47) kmax = 47;
    float J[48];
    int K = kmax + 8;
    float jp = 0.f, jc = 1e-25f;
    float inv_rho = 1.0f / rho;
    for (int kk = K; kk >= 1; kk--) {
        float jm = fmaf(2.0f * (float)kk * inv_rho, jc, -jp);
        if (kk - 1 <= kmax) J[kk - 1] = jm;
        if (fabsf(jm) > 1e24f) {
            jm *= 1e-24f; jc *= 1e-24f;
            for (int z = kk - 1; z <= kmax; z++) J[z] *= 1e-24f;
        }
        jp = jc; jc = jm;
    }
    float s = J[0];
    for (int kk = 2; kk <= kmax; kk += 2) s += 2.0f * J[kk];
    float invs = 1.0f / s;
    for (int kk = 0; kk < 48; kk++)
        g_ctab[t * 48 + kk] =
            (kk > kmax) ? 0.f : ((kk == 0 ? 1.0f : 2.0f) * J[kk] * invs);
}

// ---- packed f32x2 helpers ----
__device__ __forceinline__ ull pack2(float lo, float hi) {
    float2 t = make_float2(lo, hi);
    return *reinterpret_cast<ull*>(&t);
}
__device__ __forceinline__ float2 unpack2(ull v) {
    return *reinterpret_cast<float2*>(&v);
}
__device__ __forceinline__ void ffma2(ull& d, ull a, ull b) {
    asm("fma.rn.f32x2 %0, %1, %2, %0;" : "+l"(d) : "l"(a), "l"(b));
}
__device__ __forceinline__ ull add2(ull a, ull b) {
    ull r; asm("add.rn.f32x2 %0, %1, %2;" : "=l"(r) : "l"(a), "l"(b));
    return r;
}

// Full-row matvec: lane owns rows l and l+32 over all 64 columns.
__device__ __forceinline__ void matvec_fr(const ull* A0, const ull* A1,
                                          const float* v,
                                          float& o0, float& o1)
{
    const ulonglong2* vv = reinterpret_cast<const ulonglong2*>(v);
    ull a0[4] = {0ull, 0ull, 0ull, 0ull};
    ull a1[4] = {0ull, 0ull, 0ull, 0ull};
    #pragma unroll
    for (int q = 0; q < 16; q++) {
        ulonglong2 t = vv[q];
        ffma2(a0[(2 * q)     & 3], A0[2 * q],     t.x);
        ffma2(a0[(2 * q + 1) & 3], A0[2 * q + 1], t.y);
        ffma2(a1[(2 * q)     & 3], A1[2 * q],     t.x);
        ffma2(a1[(2 * q + 1) & 3], A1[2 * q + 1], t.y);
    }
    float2 f0 = unpack2(add2(add2(a0[0], a0[1]), add2(a0[2], a0[3])));
    o0 = f0.x + f0.y;
    float2 f1 = unpack2(add2(add2(a1[0], a1[1]), add2(a1[2], a1[3])));
    o1 = f1.x + f1.y;
}

// One Chebyshev term; phi_{k-2} carried in registers.
template <int B1, int BF>
__device__ __forceinline__ void cheb_iter(
    float (*sv)[DH], const ull* A0, const ull* A1, const float* scoef,
    float& y0, float& y1, float& p20, float& p21, float& p10, float& p11,
    int kk, int l)
{
    float o0, o1;
    matvec_fr(A0, A1, sv[B1], o0, o1);
    float cf = scoef[kk];
    float pn0 = o0 + p20;
    float pn1 = o1 + p21;
    y0 = fmaf(cf, pn0, y0);
    y1 = fmaf(cf, pn1, y1);
    p20 = p10; p21 = p11;
    p10 = pn0; p11 = pn1;
    sv[BF][l]      = pn0;
    sv[BF][l + 32] = pn1;
    __syncwarp();
}

__global__ __launch_bounds__(32, 12)
void liepe_expmv_kernel(const float* __restrict__ x,
                        const float* __restrict__ rg,
                        float* __restrict__ out)
{
    __shared__ __align__(16) float sv[2][DH];
    __shared__ float scoef[64];

    const int l = threadIdx.x;
    const int pos = blockIdx.x;

    const float r0 = __ldg(&rg[pos * DC + 0]);
    const float r1 = __ldg(&rg[pos * DC + 1]);
    const float r2 = __ldg(&rg[pos * DC + 2]);

    // ---- rho from Gram matrix; quantize UP to 0.5 steps ----
    int qi;
    {
        float g0 = __ldg(&g_gram[0]), g1 = __ldg(&g_gram[1]);
        float g2 = __ldg(&g_gram[2]), g3 = __ldg(&g_gram[3]);
        float g4 = __ldg(&g_gram[4]), g5 = __ldg(&g_gram[5]);
        float F2 = r0 * r0 * g0 + r1 * r1 * g3 + r2 * r2 * g5
                 + 2.0f * (r0 * r1 * g1 + r0 * r2 * g2 + r1 * r2 * g4);
        float rho = 0.335f * sqrtf(fmaxf(F2, 0.f));   // 0.25 edge * 1.34 safety
        qi = (int)ceilf(rho * 2.0f);
        if (qi < 1)  qi = 1;
        if (qi > 64) qi = 64;
    }
    const float rho_q = 0.5f * (float)qi;
    int kmax = (qi + 1) / 2 + 8;           // ceil(rho_q)+8
    if (kmax > 47) kmax = 47;

    // ---- coefficients from precomputed table (2 coalesced LDGs) ----
    {
        const float* row = g_ctab + (qi - 1) * 48;
        scoef[l] = __ldg(&row[l]);
        scoef[l + 32] = (l < 16) ? __ldg(&row[l + 32]) : 0.f;
    }

    // ---- e = P_sp @ x (fast path: P == I) ----
    float e0, e1;
    if (g_pident) {
        e0 = x[pos * DH + l];
        e1 = x[pos * DH + l + 32];
    } else {
        sv[0][l]      = x[pos * DH + l];
        sv[0][l + 32] = x[pos * DH + 32 + l];
        __syncwarp();
        const float4* vq4 = reinterpret_cast<const float4*>(sv[0]);
        float d0 = 0.f, d1 = 0.f;
        #pragma unroll
        for (int q = 0; q < 16; q++) {
            float4 vq = vq4[q];
            float4 p0 = __ldg(&g_psp_il[(0 * 16 + q) * 32 + l]);
            float4 p1 = __ldg(&g_psp_il[(1 * 16 + q) * 32 + l]);
            d0 = fmaf(p0.x, vq.x, fmaf(p0.y, vq.y,
                 fmaf(p0.z, vq.z, fmaf(p0.w, vq.w, d0))));
            d1 = fmaf(p1.x, vq.x, fmaf(p1.y, vq.y,
                 fmaf(p1.z, vq.z, fmaf(p1.w, vq.w, d1))));
        }
        e0 = d0; e1 = d1;
        __syncwarp();
    }
    sv[0][l]      = e0;
    sv[0][l + 32] = e1;
    __syncwarp();

    // ---- build C = (2/rho_q)*A rows l and l+32, coalesced reads ----
    ull A0[32], A1[32];
    {
        const float cs = 2.0f / rho_q;
        const float c0 = r0 * cs, c1f = r1 * cs, c2f = r2 * cs;
        #pragma unroll
        for (int rr = 0; rr < 2; rr++) {
            ull* Ad = rr ? A1 : A0;
            #pragma unroll
            for (int q = 0; q < 16; q++) {
                int base = (rr * 16 + q) * 32 + l;
                float4 v0 = __ldg(&g_skew_il[base]);
                float4 v1 = __ldg(&g_skew_il[1024 + base]);
                float4 v2 = __ldg(&g_skew_il[2048 + base]);
                float ax = fmaf(c2f, v2.x, fmaf(c1f, v1.x, c0 * v0.x));
                float ay = fmaf(c2f, v2.y, fmaf(c1f, v1.y, c0 * v0.y));
                float az = fmaf(c2f, v2.z, fmaf(c1f, v1.z, c0 * v0.z));
                float aw = fmaf(c2f, v2.w, fmaf(c1f, v1.w, c0 * v0.w));
                Ad[2 * q]     = pack2(ax, ay);
                Ad[2 * q + 1] = pack2(az, aw);
            }
        }
    }

    // ---- y = coef0*phi0; phi1 = 0.5*C*phi0 -> sv[1]; phi0 in regs ----
    float cf0 = scoef[0];
    float y0 = cf0 * e0, y1 = cf0 * e1;
    float p20 = e0, p21 = e1;
    float p10, p11;
    {
        float o0, o1;
        matvec_fr(A0, A1, sv[0], o0, o1);
        float cf1 = scoef[1];
        p10 = 0.5f * o0;
        p11 = 0.5f * o1;
        y0 = fmaf(cf1, p10, y0);
        y1 = fmaf(cf1, p11, y1);
        sv[1][l]      = p10;
        sv[1][l + 32] = p11;
        __syncwarp();
    }

    // ---- Chebyshev loop, unrolled by 2 with constant buffer indices ----
    {
        int kk = 2;
        while (kk <= kmax) {
            cheb_iter<1, 0>(sv, A0, A1, scoef, y0, y1, p20, p21, p10, p11, kk, l);
            if (++kk > kmax) break;
            cheb_iter<0, 1>(sv, A0, A1, scoef, y0, y1, p20, p21, p10, p11, kk, l);
            ++kk;
        }
    }

    out[pos * DH + l]      = y0;
    out[pos * DH + l + 32] = y1;
}

extern "C" void kernel_launch(void* const* d_in, const int* in_sizes, int n_in,
                              void* d_out, int out_size)
{
    const float* x = (const float*)d_in[0];   // [B,S,64]
    const float* r = (const float*)d_in[1];   // [B,S,3]
    const float* L = (const float*)d_in[2];   // [3,64,64]
    const float* P = (const float*)d_in[3];   // [64,64]
    float* out = (float*)d_out;

    int npos = in_sizes[0] / DH;              // B*S
    int il_total = DC * 2 * 16 * 32 + 2 * 16 * 32;   // 4096 float4 slots

    build_il_kernel<<<(il_total + 255) / 256, 256>>>(L, P);
    gram_kernel<<<1, 256>>>(P);
    coef_kernel<<<1, 64>>>();
    liepe_expmv_kernel<<<npos, 32>>>(x, r, out);
}

// round 14
// speedup vs baseline: 1.0360x; 1.0360x over previous
#include <cuda_runtime.h>
#include <math.h>

#define DH 64
#define DC 3

typedef unsigned long long ull;

// Lane-interleaved generators: float4 index ((gen*2+rr)*16+q)*32 + l holds
// S_gen[row = l+32*rr][cols 4q..4q+3], S = 0.5*(L - L^T).  3*2*16*32 float4s.
__device__ float4 g_skew_il[DC * 2 * 16 * 32];
// Lane-interleaved P_sp: float4 index (rr*16+q)*32 + l.
__device__ float4 g_psp_il[2 * 16 * 32];
// Gram matrix of generators: [S0.S0, S0.S1, S0.S2, S1.S1, S1.S2, S2.S2]
__device__ float g_gram[6];
// P == identity flag
__device__ int g_pident;
// Chebyshev coefficient table: 64 rho-quanta (rho_q = 0.5*qi, qi=1..64),
// 48 floats each: coef[k] = (k==0?1:2)*J_k(rho_q)/norm, zero beyond kmax.
__device__ float g_ctab[64 * 48];

// ONE setup kernel, grid = 18 x 256. All three jobs are independent:
//  blocks 0..15 : interleaved generator + P layouts (from L, P)
//  block 16     : Gram matrix directly from L + P-identity check
//  block 17     : Bessel/Chebyshev coefficient table (input-independent)
__global__ void setup_kernel(const float* __restrict__ L,
                             const float* __restrict__ P) {
    int blk = blockIdx.x;
    int tid = threadIdx.x;

    if (blk < 16) {
        int idx = blk * 256 + tid;
        if (idx < DC * 2 * 16 * 32) {
            int l   = idx & 31;
            int q   = (idx >> 5) & 15;
            int rr  = (idx >> 9) & 1;
            int g   = idx >> 10;
            int row = l + 32 * rr;
            const float* Lg = L + g * DH * DH;
            int c0 = 4 * q;
            float4 v;
            v.x = 0.5f * (Lg[row * DH + c0 + 0] - Lg[(c0 + 0) * DH + row]);
            v.y = 0.5f * (Lg[row * DH + c0 + 1] - Lg[(c0 + 1) * DH + row]);
            v.z = 0.5f * (Lg[row * DH + c0 + 2] - Lg[(c0 + 2) * DH + row]);
            v.w = 0.5f * (Lg[row * DH + c0 + 3] - Lg[(c0 + 3) * DH + row]);
            g_skew_il[idx] = v;
        }
        int pidx = idx - DC * 2 * 16 * 32;
        if (pidx >= 0 && pidx < 2 * 16 * 32) {
            int l   = pidx & 31;
            int q   = (pidx >> 5) & 15;
            int rr  = (pidx >> 9) & 1;
            int row = l + 32 * rr;
            const float4* pr = reinterpret_cast<const float4*>(P + row * DH);
            g_psp_il[pidx] = pr[q];
        }
        return;
    }

    if (blk == 16) {
        // Gram directly from L: S_g = 0.5*(L_g - L_g^T)
        __shared__ float red[8][6];
        __shared__ int nid[8];
        float g[6] = {0.f, 0.f, 0.f, 0.f, 0.f, 0.f};
        int notid = 0;
        for (int j = tid; j < DH * DH; j += 256) {
            int r = j >> 6, c = j & 63;
            float s0 = 0.5f * (L[j] - L[c * DH + r]);
            float s1 = 0.5f * (L[DH * DH + j] - L[DH * DH + c * DH + r]);
            float s2 = 0.5f * (L[2 * DH * DH + j] - L[2 * DH * DH + c * DH + r]);
            g[0] = fmaf(s0, s0, g[0]);
            g[1] = fmaf(s0, s1, g[1]);
            g[2] = fmaf(s0, s2, g[2]);
            g[3] = fmaf(s1, s1, g[3]);
            g[4] = fmaf(s1, s2, g[4]);
            g[5] = fmaf(s2, s2, g[5]);
            float expd = (r == c) ? 1.0f : 0.0f;
            if (P[j] != expd) notid = 1;
        }
        #pragma unroll
        for (int off = 16; off >= 1; off >>= 1) {
            #pragma unroll
            for (int i = 0; i < 6; i++)
                g[i] += __shfl_xor_sync(0xffffffffu, g[i], off);
            notid |= __shfl_xor_sync(0xffffffffu, notid, off);
        }
        if ((tid & 31) == 0) {
            #pragma unroll
            for (int i = 0; i < 6; i++) red[tid >> 5][i] = g[i];
            nid[tid >> 5] = notid;
        }
        __syncthreads();
        if (tid < 6) {
            float s = 0.f;
            #pragma unroll
            for (int w = 0; w < 8; w++) s += red[w][tid];
            g_gram[tid] = s;
        }
        if (tid == 32) {
            int n = 0;
            #pragma unroll
            for (int w = 0; w < 8; w++) n |= nid[w];
            g_pident = !n;
        }
        return;
    }

    // blk == 17: coefficient table; thread t handles qi = t+1, rho_q = 0.5*(t+1)
    {
        int t = tid;
        if (t >= 64) return;
        float rho = 0.5f * (float)(t + 1);
        int kmax = (t + 2) / 2 + 9;          // ceil(rho_q)+9
        if (kmax > 47) kmax = 47;
        float J[48];
        int K = kmax + 10;
        float jp = 0.f, jc = 1e-25f;
        float inv_rho = 1.0f / rho;
        for (int kk = K; kk >= 1; kk--) {
            float jm = fmaf(2.0f * (float)kk * inv_rho, jc, -jp);
            if (kk - 1 <= kmax) J[kk - 1] = jm;
            if (fabsf(jm) > 1e24f) {
                jm *= 1e-24f; jc *= 1e-24f;
                for (int z = kk - 1; z <= kmax; z++) J[z] *= 1e-24f;
            }
            jp = jc; jc = jm;
        }
        float s = J[0];
        for (int kk = 2; kk <= kmax; kk += 2) s += 2.0f * J[kk];
        float invs = 1.0f / s;
        for (int kk = 0; kk < 48; kk++)
            g_ctab[t * 48 + kk] =
                (kk > kmax) ? 0.f : ((kk == 0 ? 1.0f : 2.0f) * J[kk] * invs);
    }
}

// ---- packed f32x2 helpers ----
__device__ __forceinline__ ull pack2(float lo, float hi) {
    float2 t = make_float2(lo, hi);
    return *reinterpret_cast<ull*>(&t);
}
__device__ __forceinline__ float2 unpack2(ull v) {
    return *reinterpret_cast<float2*>(&v);
}
__device__ __forceinline__ void ffma2(ull& d, ull a, ull b) {
    asm("fma.rn.f32x2 %0, %1, %2, %0;" : "+l"(d) : "l"(a), "l"(b));
}
__device__ __forceinline__ ull add2(ull a, ull b) {
    ull r; asm("add.rn.f32x2 %0, %1, %2;" : "=l"(r) : "l"(a), "l"(b));
    return r;
}

// Full-row matvec: lane owns rows l and l+32 over all 64 columns.
__device__ __forceinline__ void matvec_fr(const ull* A0, const ull* A1,
                                          const float* v,
                                          float& o0, float& o1)
{
    const ulonglong2* vv = reinterpret_cast<const ulonglong2*>(v);
    ull a0[4] = {0ull, 0ull, 0ull, 0ull};
    ull a1[4] = {0ull, 0ull, 0ull, 0ull};
    #pragma unroll
    for (int q = 0; q < 16; q++) {
        ulonglong2 t = vv[q];
        ffma2(a0[(2 * q)     & 3], A0[2 * q],     t.x);
        ffma2(a0[(2 * q + 1) & 3], A0[2 * q + 1], t.y);
        ffma2(a1[(2 * q)     & 3], A1[2 * q],     t.x);
        ffma2(a1[(2 * q + 1) & 3], A1[2 * q + 1], t.y);
    }
    float2 f0 = unpack2(add2(add2(a0[0], a0[1]), add2(a0[2], a0[3])));
    o0 = f0.x + f0.y;
    float2 f1 = unpack2(add2(add2(a1[0], a1[1]), add2(a1[2], a1[3])));
    o1 = f1.x + f1.y;
}

// One Chebyshev term; phi_{k-2} carried in registers.
template <int B1, int BF>
__device__ __forceinline__ void cheb_iter(
    float (*sv)[DH], const ull* A0, const ull* A1, const float* scoef,
    float& y0, float& y1, float& p20, float& p21, float& p10, float& p11,
    int kk, int l)
{
    float o0, o1;
    matvec_fr(A0, A1, sv[B1], o0, o1);
    float cf = scoef[kk];
    float pn0 = o0 + p20;
    float pn1 = o1 + p21;
    y0 = fmaf(cf, pn0, y0);
    y1 = fmaf(cf, pn1, y1);
    p20 = p10; p21 = p11;
    p10 = pn0; p11 = pn1;
    sv[BF][l]      = pn0;
    sv[BF][l + 32] = pn1;
    __syncwarp();
}

__global__ __launch_bounds__(32, 12)
void liepe_expmv_kernel(const float* __restrict__ x,
                        const float* __restrict__ rg,
                        float* __restrict__ out)
{
    __shared__ __align__(16) float sv[2][DH];
    __shared__ float scoef[64];

    const int l = threadIdx.x;
    const int pos = blockIdx.x;

    const float r0 = __ldg(&rg[pos * DC + 0]);
    const float r1 = __ldg(&rg[pos * DC + 1]);
    const float r2 = __ldg(&rg[pos * DC + 2]);

    // ---- rho from Gram matrix; quantize UP to 0.5 steps ----
    int qi;
    {
        float g0 = __ldg(&g_gram[0]), g1 = __ldg(&g_gram[1]);
        float g2 = __ldg(&g_gram[2]), g3 = __ldg(&g_gram[3]);
        float g4 = __ldg(&g_gram[4]), g5 = __ldg(&g_gram[5]);
        float F2 = r0 * r0 * g0 + r1 * r1 * g3 + r2 * r2 * g5
                 + 2.0f * (r0 * r1 * g1 + r0 * r2 * g2 + r1 * r2 * g4);
        float rho = 0.335f * sqrtf(fmaxf(F2, 0.f));   // 0.25 edge * 1.34 safety
        qi = (int)ceilf(rho * 2.0f);
        if (qi < 1)  qi = 1;
        if (qi > 64) qi = 64;
    }
    const float rho_q = 0.5f * (float)qi;
    int kmax = (qi + 1) / 2 + 9;           // ceil(rho_q)+9
    if (kmax > 47) kmax = 47;

    // ---- coefficients from precomputed table (2 coalesced LDGs) ----
    {
        const float* row = g_ctab + (qi - 1) * 48;
        scoef[l] = __ldg(&row[l]);
        scoef[l + 32] = (l < 16) ? __ldg(&row[l + 32]) : 0.f;
    }

    // ---- e = P_sp @ x (fast path: P == I) ----
    float e0, e1;
    if (g_pident) {
        e0 = x[pos * DH + l];
        e1 = x[pos * DH + l + 32];
    } else {
        sv[0][l]      = x[pos * DH + l];
        sv[0][l + 32] = x[pos * DH + 32 + l];
        __syncwarp();
        const float4* vq4 = reinterpret_cast<const float4*>(sv[0]);
        float d0 = 0.f, d1 = 0.f;
        #pragma unroll
        for (int q = 0; q < 16; q++) {
            float4 vq = vq4[q];
            float4 p0 = __ldg(&g_psp_il[(0 * 16 + q) * 32 + l]);
            float4 p1 = __ldg(&g_psp_il[(1 * 16 + q) * 32 + l]);
            d0 = fmaf(p0.x, vq.x, fmaf(p0.y, vq.y,
                 fmaf(p0.z, vq.z, fmaf(p0.w, vq.w, d0))));
            d1 = fmaf(p1.x, vq.x, fmaf(p1.y, vq.y,
                 fmaf(p1.z, vq.z, fmaf(p1.w, vq.w, d1))));
        }
        e0 = d0; e1 = d1;
        __syncwarp();
    }
    sv[0][l]      = e0;
    sv[0][l + 32] = e1;
    __syncwarp();

    // ---- build C = (2/rho_q)*A rows l and l+32, coalesced reads ----
    ull A0[32], A1[32];
    {
        const float cs = 2.0f / rho_q;
        const float c0 = r0 * cs, c1f = r1 * cs, c2f = r2 * cs;
        #pragma unroll
        for (int rr = 0; rr < 2; rr++) {
            ull* Ad = rr ? A1 : A0;
            #pragma unroll
            for (int q = 0; q < 16; q++) {
                int base = (rr * 16 + q) * 32 + l;
                float4 v0 = __ldg(&g_skew_il[base]);
                float4 v1 = __ldg(&g_skew_il[1024 + base]);
                float4 v2 = __ldg(&g_skew_il[2048 + base]);
                float ax = fmaf(c2f, v2.x, fmaf(c1f, v1.x, c0 * v0.x));
                float ay = fmaf(c2f, v2.y, fmaf(c1f, v1.y, c0 * v0.y));
                float az = fmaf(c2f, v2.z, fmaf(c1f, v1.z, c0 * v0.z));
                float aw = fmaf(c2f, v2.w, fmaf(c1f, v1.w, c0 * v0.w));
                Ad[2 * q]     = pack2(ax, ay);
                Ad[2 * q + 1] = pack2(az, aw);
            }
        }
    }

    // ---- y = coef0*phi0; phi1 = 0.5*C*phi0 -> sv[1]; phi0 in regs ----
    float cf0 = scoef[0];
    float y0 = cf0 * e0, y1 = cf0 * e1;
    float p20 = e0, p21 = e1;
    float p10, p11;
    {
        float o0, o1;
        matvec_fr(A0, A1, sv[0], o0, o1);
        float cf1 = scoef[1];
        p10 = 0.5f * o0;
        p11 = 0.5f * o1;
        y0 = fmaf(cf1, p10, y0);
        y1 = fmaf(cf1, p11, y1);
        sv[1][l]      = p10;
        sv[1][l + 32] = p11;
        __syncwarp();
    }

    // ---- Chebyshev loop, unrolled by 2 with constant buffer indices ----
    {
        int kk = 2;
        while (kk <= kmax) {
            cheb_iter<1, 0>(sv, A0, A1, scoef, y0, y1, p20, p21, p10, p11, kk, l);
            if (++kk > kmax) break;
            cheb_iter<0, 1>(sv, A0, A1, scoef, y0, y1, p20, p21, p10, p11, kk, l);
            ++kk;
        }
    }

    out[pos * DH + l]      = y0;
    out[pos * DH + l + 32] = y1;
}

extern "C" void kernel_launch(void* const* d_in, const int* in_sizes, int n_in,
                              void* d_out, int out_size)
{
    const float* x = (const float*)d_in[0];   // [B,S,64]
    const float* r = (const float*)d_in[1];   // [B,S,3]
    const float* L = (const float*)d_in[2];   // [3,64,64]
    const float* P = (const float*)d_in[3];   // [64,64]
    float* out = (float*)d_out;

    int npos = in_sizes[0] / DH;              // B*S

    setup_kernel<<<18, 256>>>(L, P);
    liepe_expmv_kernel<<<npos, 32>>>(x, r, out);
}

// round 15
// speedup vs baseline: 1.0653x; 1.0283x over previous
#include <cuda_runtime.h>
#include <math.h>

#define DH 64
#define DC 3

typedef unsigned long long ull;

// Lane-interleaved generators with sigma-PERMUTED columns:
// float4 slot ((gen*2+rr)*16+q)*32 + l holds, for row = l+32*rr:
//   ( S[row][2q], S[row][2q+32], S[row][2q+1], S[row][2q+33] )
// matching the permuted vector storage v_perm[2i]=row i, v_perm[2i+1]=row i+32.
__device__ float4 g_skew_il[DC * 2 * 16 * 32];
// Lane-interleaved P_sp, same permuted-column mapping.
__device__ float4 g_psp_il[2 * 16 * 32];
// Gram matrix of generators: [S0.S0, S0.S1, S0.S2, S1.S1, S1.S2, S2.S2]
__device__ float g_gram[6];
// P == identity flag
__device__ int g_pident;
// Chebyshev coefficient table: 64 rho-quanta (rho_q = 0.5*qi, qi=1..64),
// 48 floats each.
__device__ float g_ctab[64 * 48];

// ONE setup kernel, grid = 18 x 256.
__global__ void setup_kernel(const float* __restrict__ L,
                             const float* __restrict__ P) {
    int blk = blockIdx.x;
    int tid = threadIdx.x;

    if (blk < 16) {
        int idx = blk * 256 + tid;
        if (idx < DC * 2 * 16 * 32) {
            int l   = idx & 31;
            int q   = (idx >> 5) & 15;
            int rr  = (idx >> 9) & 1;
            int g   = idx >> 10;
            int row = l + 32 * rr;
            const float* Lg = L + g * DH * DH;
            int ca = 2 * q, cb = 2 * q + 32, cc = 2 * q + 1, cd = 2 * q + 33;
            float4 v;
            v.x = 0.5f * (Lg[row * DH + ca] - Lg[ca * DH + row]);
            v.y = 0.5f * (Lg[row * DH + cb] - Lg[cb * DH + row]);
            v.z = 0.5f * (Lg[row * DH + cc] - Lg[cc * DH + row]);
            v.w = 0.5f * (Lg[row * DH + cd] - Lg[cd * DH + row]);
            g_skew_il[idx] = v;
        }
        int pidx = idx - DC * 2 * 16 * 32;
        if (pidx >= 0 && pidx < 2 * 16 * 32) {
            int l   = pidx & 31;
            int q   = (pidx >> 5) & 15;
            int rr  = (pidx >> 9) & 1;
            int row = l + 32 * rr;
            int ca = 2 * q, cb = 2 * q + 32, cc = 2 * q + 1, cd = 2 * q + 33;
            float4 v;
            v.x = P[row * DH + ca];
            v.y = P[row * DH + cb];
            v.z = P[row * DH + cc];
            v.w = P[row * DH + cd];
            g_psp_il[pidx] = v;
        }
        return;
    }

    if (blk == 16) {
        __shared__ float red[8][6];
        __shared__ int nid[8];
        float g[6] = {0.f, 0.f, 0.f, 0.f, 0.f, 0.f};
        int notid = 0;
        for (int j = tid; j < DH * DH; j += 256) {
            int r = j >> 6, c = j & 63;
            float s0 = 0.5f * (L[j] - L[c * DH + r]);
            float s1 = 0.5f * (L[DH * DH + j] - L[DH * DH + c * DH + r]);
            float s2 = 0.5f * (L[2 * DH * DH + j] - L[2 * DH * DH + c * DH + r]);
            g[0] = fmaf(s0, s0, g[0]);
            g[1] = fmaf(s0, s1, g[1]);
            g[2] = fmaf(s0, s2, g[2]);
            g[3] = fmaf(s1, s1, g[3]);
            g[4] = fmaf(s1, s2, g[4]);
            g[5] = fmaf(s2, s2, g[5]);
            float expd = (r == c) ? 1.0f : 0.0f;
            if (P[j] != expd) notid = 1;
        }
        #pragma unroll
        for (int off = 16; off >= 1; off >>= 1) {
            #pragma unroll
            for (int i = 0; i < 6; i++)
                g[i] += __shfl_xor_sync(0xffffffffu, g[i], off);
            notid |= __shfl_xor_sync(0xffffffffu, notid, off);
        }
        if ((tid & 31) == 0) {
            #pragma unroll
            for (int i = 0; i < 6; i++) red[tid >> 5][i] = g[i];
            nid[tid >> 5] = notid;
        }
        __syncthreads();
        if (tid < 6) {
            float s = 0.f;
            #pragma unroll
            for (int w = 0; w < 8; w++) s += red[w][tid];
            g_gram[tid] = s;
        }
        if (tid == 32) {
            int n = 0;
            #pragma unroll
            for (int w = 0; w < 8; w++) n |= nid[w];
            g_pident = !n;
        }
        return;
    }

    // blk == 17: coefficient table; thread t: qi = t+1, rho_q = 0.5*(t+1)
    {
        int t = tid;
        if (t >= 64) return;
        float rho = 0.5f * (float)(t + 1);
        int kmax = (t + 2) / 2 + 9;          // ceil(rho_q)+9
        if (kmax > 47) kmax = 47;
        float J[48];
        int K = kmax + 10;
        float jp = 0.f, jc = 1e-25f;
        float inv_rho = 1.0f / rho;
        for (int kk = K; kk >= 1; kk--) {
            float jm = fmaf(2.0f * (float)kk * inv_rho, jc, -jp);
            if (kk - 1 <= kmax) J[kk - 1] = jm;
            if (fabsf(jm) > 1e24f) {
                jm *= 1e-24f; jc *= 1e-24f;
                for (int z = kk - 1; z <= kmax; z++) J[z] *= 1e-24f;
            }
            jp = jc; jc = jm;
        }
        float s = J[0];
        for (int kk = 2; kk <= kmax; kk += 2) s += 2.0f * J[kk];
        float invs = 1.0f / s;
        for (int kk = 0; kk < 48; kk++)
            g_ctab[t * 48 + kk] =
                (kk > kmax) ? 0.f : ((kk == 0 ? 1.0f : 2.0f) * J[kk] * invs);
    }
}

// ---- packed f32x2 helpers ----
__device__ __forceinline__ ull pack2(float lo, float hi) {
    float2 t = make_float2(lo, hi);
    return *reinterpret_cast<ull*>(&t);
}
__device__ __forceinline__ float2 unpack2(ull v) {
    return *reinterpret_cast<float2*>(&v);
}
__device__ __forceinline__ void ffma2(ull& d, ull a, ull b) {
    asm("fma.rn.f32x2 %0, %1, %2, %0;" : "+l"(d) : "l"(a), "l"(b));
}
__device__ __forceinline__ ull add2(ull a, ull b) {
    ull r; asm("add.rn.f32x2 %0, %1, %2;" : "=l"(r) : "l"(a), "l"(b));
    return r;
}

// Full-row matvec over the permuted vector: lane owns rows l, l+32.
// A regs are column-permuted to match v_perm, so the code is unchanged.
__device__ __forceinline__ void matvec_fr(const ull* A0, const ull* A1,
                                          const float* v,
                                          float& o0, float& o1)
{
    const ulonglong2* vv = reinterpret_cast<const ulonglong2*>(v);
    ull a0[4] = {0ull, 0ull, 0ull, 0ull};
    ull a1[4] = {0ull, 0ull, 0ull, 0ull};
    #pragma unroll
    for (int q = 0; q < 16; q++) {
        ulonglong2 t = vv[q];
        ffma2(a0[(2 * q)     & 3], A0[2 * q],     t.x);
        ffma2(a0[(2 * q + 1) & 3], A0[2 * q + 1], t.y);
        ffma2(a1[(2 * q)     & 3], A1[2 * q],     t.x);
        ffma2(a1[(2 * q + 1) & 3], A1[2 * q + 1], t.y);
    }
    float2 f0 = unpack2(add2(add2(a0[0], a0[1]), add2(a0[2], a0[3])));
    o0 = f0.x + f0.y;
    float2 f1 = unpack2(add2(add2(a1[0], a1[1]), add2(a1[2], a1[3])));
    o1 = f1.x + f1.y;
}

// One Chebyshev term. pa holds phi_{k-2} on entry and is overwritten with
// phi_k (in-place rotation; caller alternates which register pair is passed).
// sv[B1] = phi_{k-1} (read), sv[BF] = phi_k destination (single STS.64).
template <int B1, int BF>
__device__ __forceinline__ void cheb_iter(
    float (*sv)[DH], const ull* A0, const ull* A1, const float* scoef,
    float& y0, float& y1, float& pa0, float& pa1, int kk, int l)
{
    float o0, o1;
    matvec_fr(A0, A1, sv[B1], o0, o1);
    float cf = scoef[kk];
    float pn0 = o0 + pa0;
    float pn1 = o1 + pa1;
    y0 = fmaf(cf, pn0, y0);
    y1 = fmaf(cf, pn1, y1);
    pa0 = pn0;
    pa1 = pn1;
    *reinterpret_cast<float2*>(&sv[BF][2 * l]) = make_float2(pn0, pn1);
    __syncwarp();
}

__global__ __launch_bounds__(32, 12)
void liepe_expmv_kernel(const float* __restrict__ x,
                        const float* __restrict__ rg,
                        float* __restrict__ out)
{
    __shared__ __align__(16) float sv[2][DH];
    __shared__ float scoef[64];

    const int l = threadIdx.x;
    const int pos = blockIdx.x;

    const float r0 = __ldg(&rg[pos * DC + 0]);
    const float r1 = __ldg(&rg[pos * DC + 1]);
    const float r2 = __ldg(&rg[pos * DC + 2]);

    // ---- rho from Gram matrix; quantize UP to 0.5 steps ----
    int qi;
    {
        float g0 = __ldg(&g_gram[0]), g1 = __ldg(&g_gram[1]);
        float g2 = __ldg(&g_gram[2]), g3 = __ldg(&g_gram[3]);
        float g4 = __ldg(&g_gram[4]), g5 = __ldg(&g_gram[5]);
        float F2 = r0 * r0 * g0 + r1 * r1 * g3 + r2 * r2 * g5
                 + 2.0f * (r0 * r1 * g1 + r0 * r2 * g2 + r1 * r2 * g4);
        float rho = 0.325f * sqrtf(fmaxf(F2, 0.f));   // 0.25 edge * 1.30 safety
        qi = (int)ceilf(rho * 2.0f);
        if (qi < 1)  qi = 1;
        if (qi > 64) qi = 64;
    }
    const float rho_q = 0.5f * (float)qi;
    int kmax = (qi + 1) / 2 + 9;           // ceil(rho_q)+9
    if (kmax > 47) kmax = 47;

    // ---- coefficients from precomputed table (2 coalesced LDGs) ----
    {
        const float* row = g_ctab + (qi - 1) * 48;
        scoef[l] = __ldg(&row[l]);
        scoef[l + 32] = (l < 16) ? __ldg(&row[l + 32]) : 0.f;
    }

    // ---- e = P_sp @ x (fast path: P == I) ----
    float e0, e1;
    if (g_pident) {
        e0 = x[pos * DH + l];
        e1 = x[pos * DH + l + 32];
    } else {
        // stage x in PERMUTED order, then multiply by permuted-column P
        *reinterpret_cast<float2*>(&sv[0][2 * l]) =
            make_float2(x[pos * DH + l], x[pos * DH + l + 32]);
        __syncwarp();
        const float4* vq4 = reinterpret_cast<const float4*>(sv[0]);
        float d0 = 0.f, d1 = 0.f;
        #pragma unroll
        for (int q = 0; q < 16; q++) {
            float4 vq = vq4[q];
            float4 p0 = __ldg(&g_psp_il[(0 * 16 + q) * 32 + l]);
            float4 p1 = __ldg(&g_psp_il[(1 * 16 + q) * 32 + l]);
            d0 = fmaf(p0.x, vq.x, fmaf(p0.y, vq.y,
                 fmaf(p0.z, vq.z, fmaf(p0.w, vq.w, d0))));
            d1 = fmaf(p1.x, vq.x, fmaf(p1.y, vq.y,
                 fmaf(p1.z, vq.z, fmaf(p1.w, vq.w, d1))));
        }
        e0 = d0; e1 = d1;
        __syncwarp();
    }
    // phi0 := e (permuted storage)
    *reinterpret_cast<float2*>(&sv[0][2 * l]) = make_float2(e0, e1);
    __syncwarp();

    // ---- build C = (2/rho_q)*A rows l and l+32 (permuted cols) ----
    ull A0[32], A1[32];
    {
        const float cs = 2.0f / rho_q;
        const float c0 = r0 * cs, c1f = r1 * cs, c2f = r2 * cs;
        #pragma unroll
        for (int rr = 0; rr < 2; rr++) {
            ull* Ad = rr ? A1 : A0;
            #pragma unroll
            for (int q = 0; q < 16; q++) {
                int base = (rr * 16 + q) * 32 + l;
                float4 v0 = __ldg(&g_skew_il[base]);
                float4 v1 = __ldg(&g_skew_il[1024 + base]);
                float4 v2 = __ldg(&g_skew_il[2048 + base]);
                float ax = fmaf(c2f, v2.x, fmaf(c1f, v1.x, c0 * v0.x));
                float ay = fmaf(c2f, v2.y, fmaf(c1f, v1.y, c0 * v0.y));
                float az = fmaf(c2f, v2.z, fmaf(c1f, v1.z, c0 * v0.z));
                float aw = fmaf(c2f, v2.w, fmaf(c1f, v1.w, c0 * v0.w));
                Ad[2 * q]     = pack2(ax, ay);
                Ad[2 * q + 1] = pack2(az, aw);
            }
        }
    }

    // ---- y = coef0*phi0; phi1 = 0.5*C*phi0 -> sv[1] ----
    float cf0 = scoef[0];
    float y0 = cf0 * e0, y1 = cf0 * e1;
    float pa0 = e0, pa1 = e1;            // phi_0 (becomes phi_2 in-place)
    float pb0, pb1;                      // phi_1 (becomes phi_3 in-place)
    {
        float o0, o1;
        matvec_fr(A0, A1, sv[0], o0, o1);
        float cf1 = scoef[1];
        pb0 = 0.5f * o0;
        pb1 = 0.5f * o1;
        y0 = fmaf(cf1, pb0, y0);
        y1 = fmaf(cf1, pb1, y1);
        *reinterpret_cast<float2*>(&sv[1][2 * l]) = make_float2(pb0, pb1);
        __syncwarp();
    }

    // ---- Chebyshev loop: alternate smem buffers AND register pairs ----
    {
        int kk = 2;
        while (kk <= kmax) {
            // reads phi_{k-1}=sv[1], pa=phi_{k-2} -> phi_k, writes sv[0]
            cheb_iter<1, 0>(sv, A0, A1, scoef, y0, y1, pa0, pa1, kk, l);
            if (++kk > kmax) break;
            // reads phi_{k-1}=sv[0], pb=phi_{k-2} -> phi_k, writes sv[1]
            cheb_iter<0, 1>(sv, A0, A1, scoef, y0, y1, pb0, pb1, kk, l);
            ++kk;
        }
    }

    out[pos * DH + l]      = y0;
    out[pos * DH + l + 32] = y1;
}

extern "C" void kernel_launch(void* const* d_in, const int* in_sizes, int n_in,
                              void* d_out, int out_size)
{
    const float* x = (const float*)d_in[0];   // [B,S,64]
    const float* r = (const float*)d_in[1];   // [B,S,3]
    const float* L = (const float*)d_in[2];   // [3,64,64]
    const float* P = (const float*)d_in[3];   // [64,64]
    float* out = (float*)d_out;

    int npos = in_sizes[0] / DH;              // B*S

    setup_kernel<<<18, 256>>>(L, P);
    liepe_expmv_kernel<<<npos, 32>>>(x, r, out);
}